// round 12
// baseline (speedup 1.0000x reference)
#include <cuda_runtime.h>

#define B_    16
#define C_    256
#define H_    56
#define W_    56
#define HW_   3136
#define NP_   50176   // B_*HW_
#define MID_  64
#define OC2_  144     // KK * GROUPS = 9 * 16

// scratch for per-pixel kernels, GLOBAL-PIXEL layout: [144][50176]  (~28.9 MB)
__device__ float g_weight[OC2_ * NP_];

// ---- packed f32x2 helpers ------------------------------------------------
typedef unsigned long long ull;

__device__ __forceinline__ ull pack2(float lo, float hi) {
    ull r;
    asm("mov.b64 %0, {%1, %2};" : "=l"(r) : "f"(lo), "f"(hi));
    return r;
}
__device__ __forceinline__ void unpack2(ull v, float& lo, float& hi) {
    asm("mov.b64 {%0, %1}, %2;" : "=f"(lo), "=f"(hi) : "l"(v));
}
__device__ __forceinline__ void ffma2(ull& d, ull a, ull b) {
    asm("fma.rn.f32x2 %0, %1, %2, %0;" : "+l"(d) : "l"(a), "l"(b));
}

union F4U2 { float4 f; ull u[2]; };

// ---------------------------------------------------------------------------
// Kernel 1: fused  conv1(1x1) + BN + ReLU + conv2(1x1) + bias
// 128 threads, one block = 128 global pixels (may straddle image boundary).
// Stage 1: t[64][128px]  = w1[64x256] * x[256][128px]  (8mid x 8px, FFMA2)
// Stage 2: w [144][128px]= w2[144x64] * t + b2         (6o2 x 8px, 3 passes)
// smem union (48 KB exactly): {As 8K + Bs 16K} <-> {Ts 32K + W2s 16K}
// ---------------------------------------------------------------------------
__global__ __launch_bounds__(128) void fused_conv_kernel(
    const float* __restrict__ x,
    const float* __restrict__ w1,
    const float* __restrict__ bn_gamma,
    const float* __restrict__ bn_beta,
    const float* __restrict__ bn_mean,
    const float* __restrict__ bn_var,
    const float* __restrict__ w2,
    const float* __restrict__ b2)
{
    __shared__ __align__(16) float smem_buf[12288];    // 48 KB
    float (*As)[64]   = (float(*)[64])  smem_buf;            // [32k][64o]
    float (*Bs)[128]  = (float(*)[128])(smem_buf + 2048);    // [32k][128p]
    float (*Ts)[128]  = (float(*)[128]) smem_buf;            // [64mid][128p]
    float (*W2s)[64]  = (float(*)[64]) (smem_buf + 8192);    // [64k][48slot(pad8)]

    const int tid = threadIdx.x;
    const int p0  = blockIdx.x * 128;          // global pixel base
    const int b0  = p0 / HW_;
    const int hwb = p0 - b0 * HW_;
    const int bnd = HW_ - hwb;                 // pixels >= bnd belong to b0+1

    const int ps  = tid & 15;                  // pixel slot
    const int px0 = ps * 8;                    // 8 consecutive pixels
    const int ms  = tid >> 4;                  // mid-slot 0..7

    // acc[i][jp]: mid ms*8+i, pixel pair (px0+2jp, px0+2jp+1)
    ull accp[8][4];
    #pragma unroll
    for (int i = 0; i < 8; i++)
        #pragma unroll
        for (int j = 0; j < 4; j++) accp[i][j] = 0ull;

    const int o_a = tid & 63;
    const int kh  = tid >> 6;                  // 0..1

    for (int kt = 0; kt < C_; kt += 32) {
        // load w1 tile transposed: As[k][o]
        #pragma unroll
        for (int q = 0; q < 4; q++) {
            float4 v = *(const float4*)&w1[o_a * C_ + kt + kh * 16 + q * 4];
            As[kh * 16 + q * 4 + 0][o_a] = v.x;
            As[kh * 16 + q * 4 + 1][o_a] = v.y;
            As[kh * 16 + q * 4 + 2][o_a] = v.z;
            As[kh * 16 + q * 4 + 3][o_a] = v.w;
        }
        // load x tile: Bs[k][p] (handle image-boundary straddle per float4)
        #pragma unroll
        for (int j = 0; j < 8; j++) {
            int f4i = tid + 128 * j;
            int kc  = f4i >> 5;
            int q4  = (f4i & 31) * 4;
            int ov  = (q4 >= bnd);
            int bb  = b0 + ov;
            int hw  = ov ? (q4 - bnd) : (hwb + q4);
            *(float4*)&Bs[kc][q4] =
                *(const float4*)&x[((size_t)bb * C_ + kt + kc) * HW_ + hw];
        }
        __syncthreads();

        #pragma unroll 8
        for (int kc = 0; kc < 32; kc++) {
            F4U2 B0, B1;
            B0.f = *(const float4*)&Bs[kc][px0];
            B1.f = *(const float4*)&Bs[kc][px0 + 4];
            ull tp[4] = {B0.u[0], B0.u[1], B1.u[0], B1.u[1]};
            float4 a0 = *(const float4*)&As[kc][ms * 8];
            float4 a1 = *(const float4*)&As[kc][ms * 8 + 4];
            float av[8] = {a0.x, a0.y, a0.z, a0.w, a1.x, a1.y, a1.z, a1.w};
            #pragma unroll
            for (int i = 0; i < 8; i++) {
                ull ap = pack2(av[i], av[i]);
                #pragma unroll
                for (int jp = 0; jp < 4; jp++)
                    ffma2(accp[i][jp], ap, tp[jp]);
            }
        }
        __syncthreads();
    }

    // BN (eval) + ReLU epilogue -> Ts  (Ts aliases As/Bs; all reads done)
    #pragma unroll
    for (int i = 0; i < 8; i++) {
        int o = ms * 8 + i;
        float s  = bn_gamma[o] * rsqrtf(bn_var[o] + 1e-5f);
        float sh = bn_beta[o] - bn_mean[o] * s;
        float t[8];
        #pragma unroll
        for (int jp = 0; jp < 4; jp++) {
            float lo, hi;
            unpack2(accp[i][jp], lo, hi);
            t[2 * jp]     = fmaxf(fmaf(lo, s, sh), 0.f);
            t[2 * jp + 1] = fmaxf(fmaf(hi, s, sh), 0.f);
        }
        *(float4*)&Ts[o][px0]     = make_float4(t[0], t[1], t[2], t[3]);
        *(float4*)&Ts[o][px0 + 4] = make_float4(t[4], t[5], t[6], t[7]);
    }
    __syncthreads();

    // Stage 2: three passes over 48 output rows each
    const int os = ms;                         // o2 slot group 0..7

    for (int rr = 0; rr < 3; rr++) {
        // load w2 slice transposed into W2s[k][(lr/6)*8 + lr%6]
        #pragma unroll
        for (int j = 0; j < 6; j++) {
            int lr = (tid & 15) + 16 * (j % 3);       // 0..47
            int kq = (tid >> 4) + 8 * (j / 3);        // 0..15
            int k4 = kq * 4;
            int msl = lr / 6, ii = lr - msl * 6;
            int o2 = msl * 18 + rr * 6 + ii;
            float4 v = *(const float4*)&w2[o2 * MID_ + k4];
            int lslot = msl * 8 + ii;
            W2s[k4 + 0][lslot] = v.x;
            W2s[k4 + 1][lslot] = v.y;
            W2s[k4 + 2][lslot] = v.z;
            W2s[k4 + 3][lslot] = v.w;
        }
        __syncthreads();

        // accq[ii][jp]: o2 = os*18 + rr*6 + ii, pixel pair (px0+2jp, ...)
        ull accq[6][4];
        #pragma unroll
        for (int q = 0; q < 6; q++)
            #pragma unroll
            for (int j = 0; j < 4; j++) accq[q][j] = 0ull;

        #pragma unroll 8
        for (int k = 0; k < MID_; k++) {
            F4U2 T0, T1;
            T0.f = *(const float4*)&Ts[k][px0];
            T1.f = *(const float4*)&Ts[k][px0 + 4];
            ull tp[4] = {T0.u[0], T0.u[1], T1.u[0], T1.u[1]};
            float4 wa = *(const float4*)&W2s[k][os * 8];
            float2 wb = *(const float2*)&W2s[k][os * 8 + 4];
            float wv[6] = {wa.x, wa.y, wa.z, wa.w, wb.x, wb.y};
            #pragma unroll
            for (int ii = 0; ii < 6; ii++) {
                ull wp = pack2(wv[ii], wv[ii]);
                #pragma unroll
                for (int jp = 0; jp < 4; jp++)
                    ffma2(accq[ii][jp], wp, tp[jp]);
            }
        }

        #pragma unroll
        for (int ii = 0; ii < 6; ii++) {
            int o2 = os * 18 + rr * 6 + ii;
            float bias = b2[o2];
            float o8[8];
            #pragma unroll
            for (int jp = 0; jp < 4; jp++) {
                float lo, hi;
                unpack2(accq[ii][jp], lo, hi);
                o8[2 * jp]     = lo + bias;
                o8[2 * jp + 1] = hi + bias;
            }
            float* wout = g_weight + (size_t)o2 * NP_ + p0 + px0;
            *(float4*)&wout[0] = make_float4(o8[0], o8[1], o8[2], o8[3]);
            *(float4*)&wout[4] = make_float4(o8[4], o8[5], o8[6], o8[7]);
        }
        __syncthreads();
    }
}

// ---------------------------------------------------------------------------
// Kernel 2: involution. Block = (4-row tile, group g, b). 256 threads:
// gs = tid>>4 (channel 0..15), slot = tid&15 (col quad, 14 active).
// x halo staged in smem (23 KB -> 8 blocks/SM = 64 warps, thread-cap occ).
// Per-pixel kernel weights read directly from g_weight via __ldg float4:
// identical addresses across the 16 channel-threads -> L1 broadcast, no
// smem staging, no per-thread register cache (R9's occupancy killer).
// ---------------------------------------------------------------------------
__global__ __launch_bounds__(256) void involution_kernel(
    const float* __restrict__ x,
    float* __restrict__ out)
{
    __shared__ float xs[6][16][60];   // [y0-1..y0+4][ch][col -1..58]  23.0 KB

    const int y0  = blockIdx.x * 4;
    const int g   = blockIdx.y;
    const int b   = blockIdx.z;
    const int tid = threadIdx.x;
    const int warp = tid >> 5, lane = tid & 31;

    // x halo: 6 rows x 16 channels x 58 cols (zero-padded edges)
    const float* xsrc = x + ((size_t)(b * C_ + g * 16)) * HW_;
    for (int seg = warp; seg < 96; seg += 8) {
        int row = seg >> 4, c = seg & 15;
        int gy = y0 + row - 1;
        bool rowok = ((unsigned)gy < (unsigned)H_);
        const float* src = xsrc + (size_t)c * HW_ + gy * W_;
        #pragma unroll
        for (int q = 0; q < 2; q++) {
            int col = lane + q * 32;
            if (col < 60) {
                int gx = col - 1;
                float v = 0.f;
                if (rowok && (unsigned)gx < (unsigned)W_) v = src[gx];
                xs[row][c][col] = v;
            }
        }
    }
    __syncthreads();

    const int gs   = tid >> 4;
    const int slot = tid & 15;
    if (slot >= 14) return;
    const int x0 = slot * 4;

    // weight base for this (g, b, y0, x0): per kk add kk*NP_, per row add W_
    const float* wbase = g_weight + (size_t)(g * 9) * NP_ + b * HW_ + y0 * W_ + x0;
    float* outp = out + ((size_t)(b * C_ + g * 16 + gs)) * HW_ + y0 * W_ + x0;

    #pragma unroll
    for (int r = 0; r < 4; r++) {
        const float* wr = wbase + r * W_;
        float a0 = 0.f, a1 = 0.f, a2 = 0.f, a3 = 0.f;
        #pragma unroll
        for (int dr = 0; dr < 3; dr++) {
            const float* xr = &xs[r + dr][gs][x0];
            float4 v4 = *(const float4*)xr;
            float2 v2 = *(const float2*)(xr + 4);

            float4 w0 = __ldg((const float4*)(wr + (size_t)(dr * 3 + 0) * NP_));
            a0 = fmaf(w0.x, v4.x, a0);
            a1 = fmaf(w0.y, v4.y, a1);
            a2 = fmaf(w0.z, v4.z, a2);
            a3 = fmaf(w0.w, v4.w, a3);

            float4 w1_ = __ldg((const float4*)(wr + (size_t)(dr * 3 + 1) * NP_));
            a0 = fmaf(w1_.x, v4.y, a0);
            a1 = fmaf(w1_.y, v4.z, a1);
            a2 = fmaf(w1_.z, v4.w, a2);
            a3 = fmaf(w1_.w, v2.x, a3);

            float4 w2_ = __ldg((const float4*)(wr + (size_t)(dr * 3 + 2) * NP_));
            a0 = fmaf(w2_.x, v4.z, a0);
            a1 = fmaf(w2_.y, v4.w, a1);
            a2 = fmaf(w2_.z, v2.x, a2);
            a3 = fmaf(w2_.w, v2.y, a3);
        }
        *(float4*)&outp[r * W_] = make_float4(a0, a1, a2, a3);
    }
}

extern "C" void kernel_launch(void* const* d_in, const int* in_sizes, int n_in,
                              void* d_out, int out_size)
{
    const float* x        = (const float*)d_in[0];
    const float* w1       = (const float*)d_in[1];
    const float* bn_gamma = (const float*)d_in[2];
    const float* bn_beta  = (const float*)d_in[3];
    const float* bn_mean  = (const float*)d_in[4];
    const float* bn_var   = (const float*)d_in[5];
    const float* w2       = (const float*)d_in[6];
    const float* b2       = (const float*)d_in[7];
    float* out = (float*)d_out;

    fused_conv_kernel<<<NP_ / 128, 128>>>(
        x, w1, bn_gamma, bn_beta, bn_mean, bn_var, w2, b2);

    involution_kernel<<<dim3(14, 16, 16), 256>>>(x, out);
}

// round 13
// speedup vs baseline: 1.0250x; 1.0250x over previous
#include <cuda_runtime.h>

#define B_    16
#define C_    256
#define H_    56
#define W_    56
#define HW_   3136
#define NP_   50176   // B_*HW_
#define MID_  64
#define OC2_  144     // KK * GROUPS = 9 * 16

// scratch for per-pixel kernels, layout [144][NP_]  (~28.9 MB)
__device__ float g_weight[OC2_ * NP_];

// ---- packed f32x2 helpers ------------------------------------------------
typedef unsigned long long ull;

__device__ __forceinline__ ull pack2(float lo, float hi) {
    ull r;
    asm("mov.b64 %0, {%1, %2};" : "=l"(r) : "f"(lo), "f"(hi));
    return r;
}
__device__ __forceinline__ void unpack2(ull v, float& lo, float& hi) {
    asm("mov.b64 {%0, %1}, %2;" : "=f"(lo), "=f"(hi) : "l"(v));
}
__device__ __forceinline__ void ffma2(ull& d, ull a, ull b) {
    asm("fma.rn.f32x2 %0, %1, %2, %0;" : "+l"(d) : "l"(a), "l"(b));
}

union F4U2 { float4 f; ull u[2]; };

// ---------------------------------------------------------------------------
// Kernel 1: fused  conv1(1x1) + BN + ReLU + conv2(1x1) + bias
// 128 threads, one block = 64 pixels (49 tiles/image, never straddles).
// smem 28.3 KB -> 8 blocks/SM cap, grid 784 -> ~5.3 resident blocks/SM.
// Stage 1: t[64][64px]  = w1[64x256] * x[256][64px]   (8mid x 4px, FFMA2)
// Stage 2: w [144][64px]= w2[144x64] * t + b2         (6o2 x 4px, 3 passes)
// smem union: {As 8K + Bs 8K} <-> {Ts 16K} ; W2s 12.3K after Ts.
// ---------------------------------------------------------------------------
__global__ __launch_bounds__(128) void fused_conv_kernel(
    const float* __restrict__ x,
    const float* __restrict__ w1,
    const float* __restrict__ bn_gamma,
    const float* __restrict__ bn_beta,
    const float* __restrict__ bn_mean,
    const float* __restrict__ bn_var,
    const float* __restrict__ w2,
    const float* __restrict__ b2)
{
    __shared__ __align__(16) float smem_buf[4096 + 3072];   // 28 KB
    float (*As)[64]  = (float(*)[64]) smem_buf;             // [32k][64o]   8K
    float (*Bs)[64]  = (float(*)[64])(smem_buf + 2048);     // [32k][64p]   8K
    float (*Ts)[64]  = (float(*)[64]) smem_buf;             // [64mid][64p] 16K
    float (*W2s)[48] = (float(*)[48])(smem_buf + 4096);     // [64k][48]   12K

    const int tid = threadIdx.x;
    const int blk = blockIdx.x;
    const int b   = blk / 49;
    const int hw0 = (blk % 49) * 64;
    const int pbase = b * HW_ + hw0;

    const float* xb = x + (size_t)b * C_ * HW_ + hw0;

    const int ps  = tid & 15;                  // pixel slot (4 px)
    const int px0 = ps * 4;
    const int ms  = tid >> 4;                  // mid-slot 0..7

    // accp[i][jp]: mid ms*8+i, pixel pair (px0+2jp, px0+2jp+1)
    ull accp[8][2];
    #pragma unroll
    for (int i = 0; i < 8; i++) { accp[i][0] = 0ull; accp[i][1] = 0ull; }

    const int o_a = tid & 63;
    const int kh  = tid >> 6;                  // 0..1

    for (int kt = 0; kt < C_; kt += 32) {
        // load w1 tile transposed: As[k][o]
        #pragma unroll
        for (int q = 0; q < 4; q++) {
            float4 v = *(const float4*)&w1[o_a * C_ + kt + kh * 16 + q * 4];
            As[kh * 16 + q * 4 + 0][o_a] = v.x;
            As[kh * 16 + q * 4 + 1][o_a] = v.y;
            As[kh * 16 + q * 4 + 2][o_a] = v.z;
            As[kh * 16 + q * 4 + 3][o_a] = v.w;
        }
        // load x tile: Bs[k][p]  (512 float4, 4 per thread)
        #pragma unroll
        for (int j = 0; j < 4; j++) {
            int f4i = tid + 128 * j;
            int kc  = f4i >> 4;
            int p4  = (f4i & 15) * 4;
            *(float4*)&Bs[kc][p4] =
                *(const float4*)&xb[(size_t)(kt + kc) * HW_ + p4];
        }
        __syncthreads();

        #pragma unroll 8
        for (int kc = 0; kc < 32; kc++) {
            F4U2 B0;
            B0.f = *(const float4*)&Bs[kc][px0];
            ull tp0 = B0.u[0], tp1 = B0.u[1];
            float4 a0 = *(const float4*)&As[kc][ms * 8];
            float4 a1 = *(const float4*)&As[kc][ms * 8 + 4];
            float av[8] = {a0.x, a0.y, a0.z, a0.w, a1.x, a1.y, a1.z, a1.w};
            #pragma unroll
            for (int i = 0; i < 8; i++) {
                ull ap = pack2(av[i], av[i]);
                ffma2(accp[i][0], ap, tp0);
                ffma2(accp[i][1], ap, tp1);
            }
        }
        __syncthreads();
    }

    // BN (eval) + ReLU epilogue -> Ts  (Ts aliases As/Bs; all reads done)
    #pragma unroll
    for (int i = 0; i < 8; i++) {
        int o = ms * 8 + i;
        float s  = bn_gamma[o] * rsqrtf(bn_var[o] + 1e-5f);
        float sh = bn_beta[o] - bn_mean[o] * s;
        float lo0, hi0, lo1, hi1;
        unpack2(accp[i][0], lo0, hi0);
        unpack2(accp[i][1], lo1, hi1);
        float4 t;
        t.x = fmaxf(fmaf(lo0, s, sh), 0.f);
        t.y = fmaxf(fmaf(hi0, s, sh), 0.f);
        t.z = fmaxf(fmaf(lo1, s, sh), 0.f);
        t.w = fmaxf(fmaf(hi1, s, sh), 0.f);
        *(float4*)&Ts[o][px0] = t;
    }
    __syncthreads();

    // Stage 2: three passes over 48 output rows each
    const int os = ms;

    for (int rr = 0; rr < 3; rr++) {
        // load w2 slice into W2s[k][lr], lr = msl*6+ii, o2 = msl*18+rr*6+ii
        #pragma unroll
        for (int j = 0; j < 6; j++) {
            int lr = (tid & 15) + 16 * (j % 3);       // 0..47
            int kq = (tid >> 4) + 8 * (j / 3);        // 0..15
            int k4 = kq * 4;
            int msl = lr / 6, ii = lr - msl * 6;
            int o2 = msl * 18 + rr * 6 + ii;
            float4 v = *(const float4*)&w2[o2 * MID_ + k4];
            W2s[k4 + 0][lr] = v.x;
            W2s[k4 + 1][lr] = v.y;
            W2s[k4 + 2][lr] = v.z;
            W2s[k4 + 3][lr] = v.w;
        }
        __syncthreads();

        // accq[ii][jp]: o2 = os*18 + rr*6 + ii
        ull accq[6][2];
        #pragma unroll
        for (int q = 0; q < 6; q++) { accq[q][0] = 0ull; accq[q][1] = 0ull; }

        #pragma unroll 8
        for (int k = 0; k < MID_; k++) {
            F4U2 T0;
            T0.f = *(const float4*)&Ts[k][px0];
            ull tp0 = T0.u[0], tp1 = T0.u[1];
            float2 w01 = *(const float2*)&W2s[k][os * 6];
            float2 w23 = *(const float2*)&W2s[k][os * 6 + 2];
            float2 w45 = *(const float2*)&W2s[k][os * 6 + 4];
            float wv[6] = {w01.x, w01.y, w23.x, w23.y, w45.x, w45.y};
            #pragma unroll
            for (int ii = 0; ii < 6; ii++) {
                ull wp = pack2(wv[ii], wv[ii]);
                ffma2(accq[ii][0], wp, tp0);
                ffma2(accq[ii][1], wp, tp1);
            }
        }

        #pragma unroll
        for (int ii = 0; ii < 6; ii++) {
            int o2 = os * 18 + rr * 6 + ii;
            float bias = b2[o2];
            float lo0, hi0, lo1, hi1;
            unpack2(accq[ii][0], lo0, hi0);
            unpack2(accq[ii][1], lo1, hi1);
            float4 o4 = {lo0 + bias, hi0 + bias, lo1 + bias, hi1 + bias};
            *(float4*)&g_weight[(size_t)o2 * NP_ + pbase + px0] = o4;
        }
        __syncthreads();
    }
}

// ---------------------------------------------------------------------------
// Kernel 2: involution (R7 structure — best known: 60.2us).
// Block = (4-row tile, group g, b). 256 threads:
// gs = tid>>4 (channel 0..15), slot = tid&15 (col quad, 14 active).
// Weights staged in smem (ws), read per (dr,kk) in the loop — no register
// cache (R9 regression) and no direct LDG (R12 regression).
// ---------------------------------------------------------------------------
__global__ __launch_bounds__(256) void involution_kernel(
    const float* __restrict__ x,
    float* __restrict__ out)
{
    __shared__ float ws[9][224];      // [kk][r*56+col], 4 rows contiguous   8.1 KB
    __shared__ float xs[6][16][60];   // [y0-1..y0+4][ch][col -1..58]       23.0 KB

    const int y0  = blockIdx.x * 4;
    const int g   = blockIdx.y;
    const int b   = blockIdx.z;
    const int tid = threadIdx.x;
    const int warp = tid >> 5, lane = tid & 31;

    // x halo: 6 rows x 16 channels x 58 cols (zero-padded edges)
    const float* xsrc = x + ((size_t)(b * C_ + g * 16)) * HW_;
    for (int seg = warp; seg < 96; seg += 8) {
        int row = seg >> 4, c = seg & 15;
        int gy = y0 + row - 1;
        bool rowok = ((unsigned)gy < (unsigned)H_);
        const float* src = xsrc + (size_t)c * HW_ + gy * W_;
        #pragma unroll
        for (int q = 0; q < 2; q++) {
            int col = lane + q * 32;
            if (col < 60) {
                int gx = col - 1;
                float v = 0.f;
                if (rowok && (unsigned)gx < (unsigned)W_) v = src[gx];
                xs[row][c][col] = v;
            }
        }
    }
    // per-pixel kernels: 9 kk, rows y0..y0+3 = 224 contiguous floats each
    const float* wsrc = g_weight + (size_t)(g * 9) * NP_ + b * HW_ + y0 * W_;
    for (int kk = warp; kk < 9; kk += 8) {
        #pragma unroll
        for (int q = 0; q < 7; q++) {
            int col = lane + q * 32;
            ws[kk][col] = wsrc[(size_t)kk * NP_ + col];
        }
    }
    __syncthreads();

    const int gs   = tid >> 4;
    const int slot = tid & 15;
    if (slot >= 14) return;
    const int x0 = slot * 4;

    float* outp = out + ((size_t)(b * C_ + g * 16 + gs)) * HW_ + y0 * W_ + x0;

    #pragma unroll
    for (int r = 0; r < 4; r++) {
        float a0 = 0.f, a1 = 0.f, a2 = 0.f, a3 = 0.f;
        const int wb = r * 56 + x0;
        #pragma unroll
        for (int dr = 0; dr < 3; dr++) {
            const float* xr = &xs[r + dr][gs][x0];
            float4 v4 = *(const float4*)xr;
            float2 v2 = *(const float2*)(xr + 4);

            float4 w0 = *(const float4*)&ws[dr * 3 + 0][wb];
            a0 = fmaf(w0.x, v4.x, a0);
            a1 = fmaf(w0.y, v4.y, a1);
            a2 = fmaf(w0.z, v4.z, a2);
            a3 = fmaf(w0.w, v4.w, a3);

            float4 w1_ = *(const float4*)&ws[dr * 3 + 1][wb];
            a0 = fmaf(w1_.x, v4.y, a0);
            a1 = fmaf(w1_.y, v4.z, a1);
            a2 = fmaf(w1_.z, v4.w, a2);
            a3 = fmaf(w1_.w, v2.x, a3);

            float4 w2_ = *(const float4*)&ws[dr * 3 + 2][wb];
            a0 = fmaf(w2_.x, v4.z, a0);
            a1 = fmaf(w2_.y, v4.w, a1);
            a2 = fmaf(w2_.z, v2.x, a2);
            a3 = fmaf(w2_.w, v2.y, a3);
        }
        *(float4*)&outp[r * W_] = make_float4(a0, a1, a2, a3);
    }
}

extern "C" void kernel_launch(void* const* d_in, const int* in_sizes, int n_in,
                              void* d_out, int out_size)
{
    const float* x        = (const float*)d_in[0];
    const float* w1       = (const float*)d_in[1];
    const float* bn_gamma = (const float*)d_in[2];
    const float* bn_beta  = (const float*)d_in[3];
    const float* bn_mean  = (const float*)d_in[4];
    const float* bn_var   = (const float*)d_in[5];
    const float* w2       = (const float*)d_in[6];
    const float* b2       = (const float*)d_in[7];
    float* out = (float*)d_out;

    fused_conv_kernel<<<B_ * 49, 128>>>(
        x, w1, bn_gamma, bn_beta, bn_mean, bn_var, w2, b2);

    involution_kernel<<<dim3(14, 16, 16), 256>>>(x, out);
}

// round 14
// speedup vs baseline: 1.7217x; 1.6797x over previous
#include <cuda_runtime.h>

#define B_    16
#define C_    256
#define H_    56
#define W_    56
#define HW_   3136
#define MID_  64
#define OC2_  144     // KK * GROUPS = 9 * 16

// scratch for per-pixel kernels: [B][144][HW]  (~28.9 MB)
__device__ float g_weight[B_ * OC2_ * HW_];
// pre-transposed weights (filled by prep kernel each launch)
__device__ float g_w1t[C_ * MID_];        // [k][o]   : g_w1t[k*64+o] = w1[o*256+k]
__device__ float g_w2t[3 * MID_ * 48];    // [rr][k][lr], lr=msl*6+ii -> o2=msl*18+rr*6+ii

// ---- packed f32x2 helpers ------------------------------------------------
typedef unsigned long long ull;

__device__ __forceinline__ ull pack2(float lo, float hi) {
    ull r;
    asm("mov.b64 %0, {%1, %2};" : "=l"(r) : "f"(lo), "f"(hi));
    return r;
}
__device__ __forceinline__ void unpack2(ull v, float& lo, float& hi) {
    asm("mov.b64 {%0, %1}, %2;" : "=f"(lo), "=f"(hi) : "l"(v));
}
__device__ __forceinline__ void ffma2(ull& d, ull a, ull b) {
    asm("fma.rn.f32x2 %0, %1, %2, %0;" : "+l"(d) : "l"(a), "l"(b));
}

union F4U2 { float4 f; ull u[2]; };

// ---- cp.async helpers ----------------------------------------------------
__device__ __forceinline__ void cp16(void* smem, const void* gmem) {
    unsigned sa = (unsigned)__cvta_generic_to_shared(smem);
    asm volatile("cp.async.ca.shared.global [%0], [%1], 16;" :: "r"(sa), "l"(gmem));
}
__device__ __forceinline__ void cp_commit() {
    asm volatile("cp.async.commit_group;");
}
template <int N> __device__ __forceinline__ void cp_wait() {
    asm volatile("cp.async.wait_group %0;" :: "n"(N));
}

// ---------------------------------------------------------------------------
// Prep: transpose w1 -> g_w1t[k][o]; permute w2 -> g_w2t[rr][k][lr]
// ---------------------------------------------------------------------------
__global__ void prep_kernel(const float* __restrict__ w1,
                            const float* __restrict__ w2)
{
    int idx = blockIdx.x * 256 + threadIdx.x;
    if (idx < C_ * MID_) {
        int k = idx >> 6, o = idx & 63;
        g_w1t[k * MID_ + o] = w1[o * C_ + k];
    }
    if (idx < 3 * MID_ * 48) {
        int rr  = idx / (MID_ * 48);
        int rem = idx - rr * (MID_ * 48);
        int k   = rem / 48, lr = rem - (rem / 48) * 48;
        int msl = lr / 6, ii = lr - msl * 6;
        int o2  = msl * 18 + rr * 6 + ii;
        g_w2t[idx] = w2[o2 * MID_ + k];
    }
}

// ---------------------------------------------------------------------------
// Kernel 1: fused conv1(1x1)+BN+ReLU+conv2(1x1)+bias, cp.async 2-stage pipe.
// 128 threads, one block = 64 pixels. smem 32 KB -> 7 blocks/SM.
// Stage 1: t[64][64px]  = w1^T tiles * x tiles      (8mid x 4px, FFMA2)
// Stage 2: w [144][64px]= w2 * t + b2               (6o2 x 4px, 3 passes)
// smem: ping-pong {As|Bs}x2 = 32KB; stage2 aliases: Ts 16K + W2s 12K.
// ---------------------------------------------------------------------------
__global__ __launch_bounds__(128) void fused_conv_kernel(
    const float* __restrict__ x,
    const float* __restrict__ bn_gamma,
    const float* __restrict__ bn_beta,
    const float* __restrict__ bn_mean,
    const float* __restrict__ bn_var,
    const float* __restrict__ b2)
{
    __shared__ __align__(16) float buf[8192];   // 32 KB
    // stage1: buffer s: As = buf + s*4096 ([32k][64o]), Bs = +2048 ([32k][64p])
    // stage2: Ts = buf[0..4095] ([64mid][64p]), W2s = buf+4096 ([64k][48])

    const int tid = threadIdx.x;
    const int blk = blockIdx.x;
    const int b   = blk / 49;
    const int hw0 = (blk % 49) * 64;

    const float* xb = x + (size_t)b * C_ * HW_ + hw0;

    const int ps  = tid & 15;
    const int px0 = ps * 4;
    const int ms  = tid >> 4;                  // mid-slot 0..7

    ull accp[8][2];
    #pragma unroll
    for (int i = 0; i < 8; i++) { accp[i][0] = 0ull; accp[i][1] = 0ull; }

    // ---- prefetch chunk 0 ----
    {
        float* As = buf;  float* Bs = buf + 2048;
        #pragma unroll
        for (int j = 0; j < 4; j++) {
            int off = (tid + 128 * j) * 4;
            cp16(As + off, g_w1t + off);           // kt=0
        }
        #pragma unroll
        for (int j = 0; j < 4; j++) {
            int f4i = tid + 128 * j;
            int kc  = f4i >> 4, p4 = (f4i & 15) * 4;
            cp16(Bs + kc * 64 + p4, xb + (size_t)kc * HW_ + p4);
        }
        cp_commit();
    }

    for (int c = 0; c < 8; c++) {
        if (c < 7) {
            int sb = (c + 1) & 1;
            float* As = buf + sb * 4096;
            float* Bs = As + 2048;
            const float* w1c = g_w1t + (c + 1) * 2048;
            int ktn = (c + 1) * 32;
            #pragma unroll
            for (int j = 0; j < 4; j++) {
                int off = (tid + 128 * j) * 4;
                cp16(As + off, w1c + off);
            }
            #pragma unroll
            for (int j = 0; j < 4; j++) {
                int f4i = tid + 128 * j;
                int kc  = f4i >> 4, p4 = (f4i & 15) * 4;
                cp16(Bs + kc * 64 + p4, xb + (size_t)(ktn + kc) * HW_ + p4);
            }
            cp_commit();
            cp_wait<1>();
        } else {
            cp_wait<0>();
        }
        __syncthreads();

        const float* As = buf + (c & 1) * 4096;
        const float* Bs = As + 2048;

        #pragma unroll 8
        for (int kc = 0; kc < 32; kc++) {
            F4U2 B0;
            B0.f = *(const float4*)&Bs[kc * 64 + px0];
            ull tp0 = B0.u[0], tp1 = B0.u[1];
            float4 a0 = *(const float4*)&As[kc * 64 + ms * 8];
            float4 a1 = *(const float4*)&As[kc * 64 + ms * 8 + 4];
            float av[8] = {a0.x, a0.y, a0.z, a0.w, a1.x, a1.y, a1.z, a1.w};
            #pragma unroll
            for (int i = 0; i < 8; i++) {
                ull ap = pack2(av[i], av[i]);
                ffma2(accp[i][0], ap, tp0);
                ffma2(accp[i][1], ap, tp1);
            }
        }
        __syncthreads();
    }

    // BN (eval) + ReLU epilogue -> Ts
    float (*Ts)[64] = (float(*)[64])buf;
    #pragma unroll
    for (int i = 0; i < 8; i++) {
        int o = ms * 8 + i;
        float s  = bn_gamma[o] * rsqrtf(bn_var[o] + 1e-5f);
        float sh = bn_beta[o] - bn_mean[o] * s;
        float lo0, hi0, lo1, hi1;
        unpack2(accp[i][0], lo0, hi0);
        unpack2(accp[i][1], lo1, hi1);
        float4 t;
        t.x = fmaxf(fmaf(lo0, s, sh), 0.f);
        t.y = fmaxf(fmaf(hi0, s, sh), 0.f);
        t.z = fmaxf(fmaf(lo1, s, sh), 0.f);
        t.w = fmaxf(fmaf(hi1, s, sh), 0.f);
        *(float4*)&Ts[o][px0] = t;
    }
    __syncthreads();

    // Stage 2: three passes over 48 output rows each
    float* W2s = buf + 4096;                   // [64][48]
    const int os = ms;

    for (int rr = 0; rr < 3; rr++) {
        const float4* src = (const float4*)(g_w2t + rr * (MID_ * 48));
        #pragma unroll
        for (int j = 0; j < 6; j++) {
            int i4 = tid + 128 * j;            // 0..767
            ((float4*)W2s)[i4] = src[i4];
        }
        __syncthreads();

        ull accq[6][2];
        #pragma unroll
        for (int q = 0; q < 6; q++) { accq[q][0] = 0ull; accq[q][1] = 0ull; }

        #pragma unroll 8
        for (int k = 0; k < MID_; k++) {
            F4U2 T0;
            T0.f = *(const float4*)&Ts[k][px0];
            ull tp0 = T0.u[0], tp1 = T0.u[1];
            const float* wk = W2s + k * 48 + os * 6;
            float2 w01 = *(const float2*)(wk);
            float2 w23 = *(const float2*)(wk + 2);
            float2 w45 = *(const float2*)(wk + 4);
            float wv[6] = {w01.x, w01.y, w23.x, w23.y, w45.x, w45.y};
            #pragma unroll
            for (int ii = 0; ii < 6; ii++) {
                ull wp = pack2(wv[ii], wv[ii]);
                ffma2(accq[ii][0], wp, tp0);
                ffma2(accq[ii][1], wp, tp1);
            }
        }

        #pragma unroll
        for (int ii = 0; ii < 6; ii++) {
            int o2 = os * 18 + rr * 6 + ii;
            float bias = b2[o2];
            float lo0, hi0, lo1, hi1;
            unpack2(accq[ii][0], lo0, hi0);
            unpack2(accq[ii][1], lo1, hi1);
            float4 o4 = {lo0 + bias, hi0 + bias, lo1 + bias, hi1 + bias};
            *(float4*)&g_weight[((size_t)b * OC2_ + o2) * HW_ + hw0 + px0] = o4;
        }
        __syncthreads();
    }
}

// ---------------------------------------------------------------------------
// Kernel 2: involution — exact R7 structure (best measured: 60.2us).
// Block = (4-row tile, group g, b). 256 threads:
// gs = tid>>4 (channel 0..15), slot = tid&15 (col quad, 14 active).
// ---------------------------------------------------------------------------
__global__ __launch_bounds__(256) void involution_kernel(
    const float* __restrict__ x,
    float* __restrict__ out)
{
    __shared__ float ws[9][224];      // [kk][r*56+col]                8.1 KB
    __shared__ float xs[6][16][60];   // [y0-1..y0+4][ch][col -1..58] 23.0 KB

    const int y0  = blockIdx.x * 4;
    const int g   = blockIdx.y;
    const int b   = blockIdx.z;
    const int tid = threadIdx.x;
    const int warp = tid >> 5, lane = tid & 31;

    const float* xsrc = x + ((size_t)(b * C_ + g * 16)) * HW_;
    for (int seg = warp; seg < 96; seg += 8) {
        int row = seg >> 4, c = seg & 15;
        int gy = y0 + row - 1;
        bool rowok = ((unsigned)gy < (unsigned)H_);
        const float* src = xsrc + (size_t)c * HW_ + gy * W_;
        #pragma unroll
        for (int q = 0; q < 2; q++) {
            int col = lane + q * 32;
            if (col < 60) {
                int gx = col - 1;
                float v = 0.f;
                if (rowok && (unsigned)gx < (unsigned)W_) v = src[gx];
                xs[row][c][col] = v;
            }
        }
    }
    const float* wsrc = g_weight + ((size_t)(b * OC2_ + g * 9)) * HW_ + y0 * W_;
    for (int kk = warp; kk < 9; kk += 8) {
        #pragma unroll
        for (int q = 0; q < 7; q++) {
            int col = lane + q * 32;
            ws[kk][col] = wsrc[(size_t)kk * HW_ + col];
        }
    }
    __syncthreads();

    const int gs   = tid >> 4;
    const int slot = tid & 15;
    if (slot >= 14) return;
    const int x0 = slot * 4;

    float* outp = out + ((size_t)(b * C_ + g * 16 + gs)) * HW_ + y0 * W_ + x0;

    #pragma unroll
    for (int r = 0; r < 4; r++) {
        float a0 = 0.f, a1 = 0.f, a2 = 0.f, a3 = 0.f;
        const int wb = r * 56 + x0;
        #pragma unroll
        for (int dr = 0; dr < 3; dr++) {
            const float* xr = &xs[r + dr][gs][x0];
            float4 v4 = *(const float4*)xr;
            float2 v2 = *(const float2*)(xr + 4);

            float4 w0 = *(const float4*)&ws[dr * 3 + 0][wb];
            a0 = fmaf(w0.x, v4.x, a0);
            a1 = fmaf(w0.y, v4.y, a1);
            a2 = fmaf(w0.z, v4.z, a2);
            a3 = fmaf(w0.w, v4.w, a3);

            float4 w1_ = *(const float4*)&ws[dr * 3 + 1][wb];
            a0 = fmaf(w1_.x, v4.y, a0);
            a1 = fmaf(w1_.y, v4.z, a1);
            a2 = fmaf(w1_.z, v4.w, a2);
            a3 = fmaf(w1_.w, v2.x, a3);

            float4 w2_ = *(const float4*)&ws[dr * 3 + 2][wb];
            a0 = fmaf(w2_.x, v4.z, a0);
            a1 = fmaf(w2_.y, v4.w, a1);
            a2 = fmaf(w2_.z, v2.x, a2);
            a3 = fmaf(w2_.w, v2.y, a3);
        }
        *(float4*)&outp[r * W_] = make_float4(a0, a1, a2, a3);
    }
}

extern "C" void kernel_launch(void* const* d_in, const int* in_sizes, int n_in,
                              void* d_out, int out_size)
{
    const float* x        = (const float*)d_in[0];
    const float* w1       = (const float*)d_in[1];
    const float* bn_gamma = (const float*)d_in[2];
    const float* bn_beta  = (const float*)d_in[3];
    const float* bn_mean  = (const float*)d_in[4];
    const float* bn_var   = (const float*)d_in[5];
    const float* w2       = (const float*)d_in[6];
    const float* b2       = (const float*)d_in[7];
    float* out = (float*)d_out;

    prep_kernel<<<64, 256>>>(w1, w2);

    fused_conv_kernel<<<B_ * 49, 128>>>(
        x, bn_gamma, bn_beta, bn_mean, bn_var, b2);

    involution_kernel<<<dim3(14, 16, 16), 256>>>(x, out);
}